// round 11
// baseline (speedup 1.0000x reference)
#include <cuda_runtime.h>
#include <cuda_bf16.h>
#include <math.h>
#include <stdint.h>

// Problem dims (fixed): x [2,2048,2048] -> T=4096 tokens, H=2048, I=8192
#define T_TOK 4096
#define HDIM  2048
#define IDIM  8192
#define NGATE 16384   // 2*I rows in w_gate
#define PITCH 80      // padded smem row pitch (bytes) for 64B k-chunks

// ---------------- device scratch (static, allocation-free) ----------------
__device__ double        d_part[3072];
__device__ float         d_wscale[2];
__device__ float         d_winv[2];
__device__ __nv_bfloat16 d_wqg[(long long)NGATE * HDIM];   // ternary gate/up (bf16 ints)
__device__ __nv_bfloat16 d_wqd[(long long)HDIM * IDIM];
__device__ signed char   d_wqg8[(long long)NGATE * HDIM];  // same values, int8
__device__ signed char   d_wqd8[(long long)HDIM * IDIM];
__device__ __nv_bfloat16 d_xq[(long long)T_TOK * HDIM];    // quant acts L1
__device__ signed char   d_xq8[(long long)T_TOK * HDIM];
__device__ float         d_as1[T_TOK];
__device__ float         d_h[(long long)T_TOK * IDIM];     // SwiGLU output (fp32)
__device__ __nv_bfloat16 d_hq[(long long)T_TOK * IDIM];    // quant acts L2
__device__ signed char   d_hq8[(long long)T_TOK * IDIM];
__device__ float         d_as2[T_TOK];

// ---------------- PTX helpers (base PTX only) ----------------
__device__ __forceinline__ uint32_t smem_u32(const void* p) {
    return (uint32_t)__cvta_generic_to_shared(p);
}
__device__ __forceinline__ void cpa16(uint32_t s, const void* g) {
    asm volatile("cp.async.cg.shared.global [%0], [%1], 16;" :: "r"(s), "l"(g));
}
__device__ __forceinline__ void cp_commit() {
    asm volatile("cp.async.commit_group;");
}
__device__ __forceinline__ void ldsm4(uint32_t* r, uint32_t a) {
    asm volatile("ldmatrix.sync.aligned.m8n8.x4.shared.b16 {%0,%1,%2,%3}, [%4];"
        : "=r"(r[0]), "=r"(r[1]), "=r"(r[2]), "=r"(r[3]) : "r"(a));
}
__device__ __forceinline__ void mma_bf16(float* c, const uint32_t* a, const uint32_t* b) {
    asm volatile(
        "mma.sync.aligned.m16n8k16.row.col.f32.bf16.bf16.f32 "
        "{%0,%1,%2,%3}, {%4,%5,%6,%7}, {%8,%9}, {%0,%1,%2,%3};"
        : "+f"(c[0]), "+f"(c[1]), "+f"(c[2]), "+f"(c[3])
        : "r"(a[0]), "r"(a[1]), "r"(a[2]), "r"(a[3]), "r"(b[0]), "r"(b[1]));
}
__device__ __forceinline__ float silu_mul(float g, float v) {
    return g / (1.f + expf(-g)) * v;
}

// ---------------- scalar pre-passes ----------------
__global__ void k_abssum2(const float* __restrict__ wg, const float* __restrict__ wd) {
    const float* w; long long n; int bid, nb;
    if (blockIdx.x < 2048) { w = wg; n = (long long)NGATE * HDIM; bid = blockIdx.x; nb = 2048; }
    else                   { w = wd; n = (long long)HDIM * IDIM;  bid = blockIdx.x - 2048; nb = 1024; }
    float s = 0.f;
    long long stride = (long long)nb * 256;
    for (long long i = (long long)bid * 256 + threadIdx.x; i < n; i += stride)
        s += fabsf(w[i]);
    #pragma unroll
    for (int o = 16; o > 0; o >>= 1) s += __shfl_xor_sync(0xffffffffu, s, o);
    __shared__ double sb[8];
    int wid = threadIdx.x >> 5, lane = threadIdx.x & 31;
    if (lane == 0) sb[wid] = (double)s;
    __syncthreads();
    if (threadIdx.x == 0) {
        double t = 0.0;
        #pragma unroll
        for (int i = 0; i < 8; i++) t += sb[i];
        d_part[blockIdx.x] = t;
    }
}

__global__ void k_wscale() {
    double s0 = 0.0, s1 = 0.0;
    for (int i = threadIdx.x; i < 2048; i += 256) s0 += d_part[i];
    for (int i = 2048 + threadIdx.x; i < 3072; i += 256) s1 += d_part[i];
    #pragma unroll
    for (int o = 16; o > 0; o >>= 1) {
        s0 += __shfl_xor_sync(0xffffffffu, s0, o);
        s1 += __shfl_xor_sync(0xffffffffu, s1, o);
    }
    __shared__ double sb0[8], sb1[8];
    int wid = threadIdx.x >> 5, lane = threadIdx.x & 31;
    if (lane == 0) { sb0[wid] = s0; sb1[wid] = s1; }
    __syncthreads();
    if (threadIdx.x == 0) {
        double t0 = 0.0, t1 = 0.0;
        #pragma unroll
        for (int i = 0; i < 8; i++) { t0 += sb0[i]; t1 += sb1[i]; }
        float m0 = (float)(t0 / (double)((long long)NGATE * HDIM));
        float m1 = (float)(t1 / (double)((long long)HDIM * IDIM));
        float sc0 = 1.f / fmaxf(m0, 1e-5f);
        float sc1 = 1.f / fmaxf(m1, 1e-5f);
        d_wscale[0] = sc0; d_wscale[1] = sc1;
        d_winv[0] = 1.f / sc0; d_winv[1] = 1.f / sc1;
    }
}

// ternarize -> bf16 AND int8
__global__ void k_wquant2(const float4* __restrict__ wg, const float4* __restrict__ wd) {
    const float4* w; long long n4; int which, bid, nb;
    if (blockIdx.x < 4096) { w = wg; n4 = (long long)NGATE * HDIM / 4; which = 0; bid = blockIdx.x; nb = 4096; }
    else                   { w = wd; n4 = (long long)HDIM * IDIM / 4;  which = 1; bid = blockIdx.x - 4096; nb = 2048; }
    float s = d_wscale[which];
    __nv_bfloat162* q2 = reinterpret_cast<__nv_bfloat162*>(which ? d_wqd : d_wqg);
    char4* q8 = reinterpret_cast<char4*>(which ? d_wqd8 : d_wqg8);
    long long stride = (long long)nb * 256;
    for (long long i = (long long)bid * 256 + threadIdx.x; i < n4; i += stride) {
        float4 v = w[i];
        float a = fminf(fmaxf(rintf(v.x * s), -1.f), 1.f);
        float b = fminf(fmaxf(rintf(v.y * s), -1.f), 1.f);
        float c = fminf(fmaxf(rintf(v.z * s), -1.f), 1.f);
        float d = fminf(fmaxf(rintf(v.w * s), -1.f), 1.f);
        q2[i * 2 + 0] = __floats2bfloat162_rn(a, b);
        q2[i * 2 + 1] = __floats2bfloat162_rn(c, d);
        q8[i] = make_char4((signed char)a, (signed char)b, (signed char)c, (signed char)d);
    }
}

// ---------------- block reduction helper ----------------
__device__ __forceinline__ float block_reduce(float v, bool isMax) {
    __shared__ float sb[8];
    __syncthreads();
    #pragma unroll
    for (int o = 16; o > 0; o >>= 1) {
        float t = __shfl_xor_sync(0xffffffffu, v, o);
        v = isMax ? fmaxf(v, t) : (v + t);
    }
    int wid = threadIdx.x >> 5, lane = threadIdx.x & 31;
    if (lane == 0) sb[wid] = v;
    __syncthreads();
    float r;
    if (isMax) {
        r = fmaxf(fmaxf(fmaxf(sb[0], sb[1]), fmaxf(sb[2], sb[3])),
                  fmaxf(fmaxf(sb[4], sb[5]), fmaxf(sb[6], sb[7])));
    } else {
        r = sb[0] + sb[1] + sb[2] + sb[3] + sb[4] + sb[5] + sb[6] + sb[7];
    }
    return r;
}

// ---------------- RMSNorm + per-token int8 quant (bf16 + s8 out) -----------
template <int HID, int VPT>
__global__ void __launch_bounds__(256) k_actquant(
    const float* __restrict__ x, const float* __restrict__ g,
    __nv_bfloat16* __restrict__ q16, signed char* __restrict__ q8,
    float* __restrict__ ascale)
{
    long long t = blockIdx.x;
    const float* xr = x + t * HID;
    float v[VPT];
    float ss = 0.f;
    #pragma unroll
    for (int j = 0; j < VPT; j++) {
        float f = xr[threadIdx.x + j * 256];
        v[j] = f;
        ss += f * f;
    }
    float var = block_reduce(ss, false) * (1.f / (float)HID);
    float r = rsqrtf(var + 1e-5f);
    float amax = 0.f;
    #pragma unroll
    for (int j = 0; j < VPT; j++) {
        float xn = v[j] * r * g[threadIdx.x + j * 256];
        v[j] = xn;
        amax = fmaxf(amax, fabsf(xn));
    }
    amax = block_reduce(amax, true);
    float s = 127.f / fmaxf(amax, 1e-5f);
    __nv_bfloat16* qr = q16 + t * HID;
    signed char* qr8 = q8 + t * HID;
    #pragma unroll
    for (int j = 0; j < VPT; j++) {
        float qf = fminf(fmaxf(rintf(v[j] * s), -128.f), 127.f);
        qr[threadIdx.x + j * 256] = __float2bfloat16(qf);
        qr8[threadIdx.x + j * 256] = (signed char)qf;
    }
    if (threadIdx.x == 0) ascale[t] = 1.f / s;
}

// =====================================================================
// GEMM1 heterogeneous: grid 4096 blocks x 256 thr.
// Pattern per 16 blocks: 11 HMMA (64 h-cols each) + 5 dp4a (64 h-cols).
// HMMA tiles cover h-cols [0,5632); dp4a tiles cover [5632,8192).
// HMMA stage (20480B x2): A16 @0 (128x80) | G16 @10240 (64x80) | V16 @15360
// dp4a (single buffer, 16KB): As @0 | Bg @8192 | Bv @12288
// =====================================================================
#define S1 20480

__global__ void __launch_bounds__(256, 3) k_gemm1_mix() {
    extern __shared__ char smem[];
    const int tid = threadIdx.x;
    const int bx = blockIdx.x;
    const int i16 = bx & 15;
    const int grp = bx >> 4;        // 0..255
    const int mrow = grp >> 3, sub = grp & 7;
    const int mBase = mrow * 128;

    if (i16 < 11) {
        // ======================= HMMA block =======================
        const int nBase = (sub * 11 + i16) * 64;    // h-col base, [0,5632)
        const int wid = tid >> 5, l = tid & 31;
        const int wm = wid >> 2, wn = wid & 3;      // 2 x 4 warps
        const uint32_t sb = smem_u32(smem);

        const char* Ag16 = (const char*)d_xq  + (long long)mBase * (HDIM * 2);
        const char* Gg16 = (const char*)d_wqg + (long long)nBase * (HDIM * 2);
        const char* Vg16 = (const char*)d_wqg + (long long)(nBase + IDIM) * (HDIM * 2);

        float accg[4][2][4] = {};
        float accv[4][2][4] = {};

        const uint32_t aoff = (uint32_t)(wm * 64 + (l & 15)) * PITCH + (l >> 4) * 16;
        const uint32_t boff = (uint32_t)(wn * 16 + ((l >> 4) << 3) + (l & 7)) * PITCH
                            + ((l >> 3) & 1) * 16;

        #define G1H_LOAD(buf, kt)                                                    \
        {                                                                            \
            const uint32_t st = sb + (buf) * S1;                                     \
            const int row = tid >> 2, seg = tid & 3;                                 \
            const long long go = (long long)row * (HDIM*2) + (kt) * 64 + seg * 16;   \
            const uint32_t so = (uint32_t)row * PITCH + seg * 16;                    \
            cpa16(st + so, Ag16 + go);                                               \
            cpa16(st + (uint32_t)(row + 64) * PITCH + seg * 16,                      \
                  Ag16 + (long long)(row + 64) * (HDIM*2) + (kt) * 64 + seg * 16);   \
            cpa16(st + 10240 + so, Gg16 + go);                                       \
            cpa16(st + 15360 + so, Vg16 + go);                                       \
            cp_commit();                                                             \
        }

        const int NK = HDIM / 32;   // 64 chunks of 32 bf16
        G1H_LOAD(0, 0);
        for (int kt = 0; kt < NK; kt++) {
            const int buf = kt & 1;
            if (kt + 1 < NK) {
                G1H_LOAD(buf ^ 1, kt + 1);
                asm volatile("cp.async.wait_group 1;");
            } else {
                asm volatile("cp.async.wait_group 0;");
            }
            __syncthreads();
            const uint32_t As = sb + buf * S1;
            const uint32_t Gs = As + 10240, Vs = As + 15360;
            #pragma unroll
            for (int ks = 0; ks < 2; ks++) {
                uint32_t bg[4], bv[4];
                ldsm4(bg, Gs + boff + ks * 32);
                ldsm4(bv, Vs + boff + ks * 32);
                #pragma unroll
                for (int mf = 0; mf < 4; mf++) {
                    uint32_t a[4];
                    ldsm4(a, As + aoff + mf * (16 * PITCH) + ks * 32);
                    #pragma unroll
                    for (int nf = 0; nf < 2; nf++) {
                        mma_bf16(accg[mf][nf], a, &bg[nf * 2]);
                        mma_bf16(accv[mf][nf], a, &bv[nf * 2]);
                    }
                }
            }
            __syncthreads();
        }
        #undef G1H_LOAD

        const float wiv = d_winv[0];
        #pragma unroll
        for (int mf = 0; mf < 4; mf++) {
            const int r0 = mBase + wm * 64 + mf * 16 + (l >> 2);
            const float s0 = d_as1[r0] * wiv;
            const float s1 = d_as1[r0 + 8] * wiv;
            float* h0 = d_h + (long long)r0 * IDIM;
            float* h1 = d_h + (long long)(r0 + 8) * IDIM;
            #pragma unroll
            for (int nf = 0; nf < 2; nf++) {
                const int c0 = nBase + wn * 16 + nf * 8 + (l & 3) * 2;
                float2 o0, o1;
                o0.x = silu_mul(accg[mf][nf][0] * s0, accv[mf][nf][0] * s0);
                o0.y = silu_mul(accg[mf][nf][1] * s0, accv[mf][nf][1] * s0);
                o1.x = silu_mul(accg[mf][nf][2] * s1, accv[mf][nf][2] * s1);
                o1.y = silu_mul(accg[mf][nf][3] * s1, accv[mf][nf][3] * s1);
                *(float2*)(h0 + c0) = o0;
                *(float2*)(h1 + c0) = o1;
            }
        }
    } else {
        // ======================= dp4a block =======================
        const int nBase = (88 + sub * 5 + (i16 - 11)) * 64;   // h-cols [5632,8192)
        const int KI = HDIM / 4;   // 512 ints per row
        const int* Aq = (const int*)d_xq8;
        const int* Wq = (const int*)d_wqg8;
        const int* Ab = Aq + (long long)mBase * KI;
        const int* Gb = Wq + (long long)nBase * KI;
        const int* Vb = Wq + (long long)(nBase + IDIM) * KI;

        int (*As)[128] = (int(*)[128])(smem);           // 8KB
        int (*Bgs)[64] = (int(*)[64])(smem + 8192);     // 4KB
        int (*Bvs)[64] = (int(*)[64])(smem + 12288);    // 4KB

        const int tx = tid & 15, ty = tid >> 4;
        int accg[8][4] = {};
        int accv[8][4] = {};

        for (int kt = 0; kt < HDIM / 64; kt++) {
            const int k0 = kt * 16;
            #pragma unroll
            for (int rr = 0; rr < 2; rr++) {
                int u = tid + rr * 256;
                int m = u >> 2, c = u & 3;
                int4 val = *(const int4*)(Ab + (long long)m * KI + k0 + c * 4);
                As[c * 4 + 0][m] = val.x; As[c * 4 + 1][m] = val.y;
                As[c * 4 + 2][m] = val.z; As[c * 4 + 3][m] = val.w;
            }
            {
                int n = tid >> 2, c = tid & 3;
                int4 vg = *(const int4*)(Gb + (long long)n * KI + k0 + c * 4);
                Bgs[c * 4 + 0][n] = vg.x; Bgs[c * 4 + 1][n] = vg.y;
                Bgs[c * 4 + 2][n] = vg.z; Bgs[c * 4 + 3][n] = vg.w;
                int4 vv = *(const int4*)(Vb + (long long)n * KI + k0 + c * 4);
                Bvs[c * 4 + 0][n] = vv.x; Bvs[c * 4 + 1][n] = vv.y;
                Bvs[c * 4 + 2][n] = vv.z; Bvs[c * 4 + 3][n] = vv.w;
            }
            __syncthreads();
            #pragma unroll
            for (int kk = 0; kk < 16; kk++) {
                const int4 a0 = *(const int4*)(&As[kk][ty * 8]);
                const int4 a1 = *(const int4*)(&As[kk][ty * 8 + 4]);
                const int4 bg4 = *(const int4*)(&Bgs[kk][tx * 4]);
                const int4 bv4 = *(const int4*)(&Bvs[kk][tx * 4]);
                int a[8] = {a0.x, a0.y, a0.z, a0.w, a1.x, a1.y, a1.z, a1.w};
                int bg[4] = {bg4.x, bg4.y, bg4.z, bg4.w};
                int bv[4] = {bv4.x, bv4.y, bv4.z, bv4.w};
                #pragma unroll
                for (int ii = 0; ii < 8; ii++) {
                    #pragma unroll
                    for (int j = 0; j < 4; j++) {
                        accg[ii][j] = __dp4a(a[ii], bg[j], accg[ii][j]);
                        accv[ii][j] = __dp4a(a[ii], bv[j], accv[ii][j]);
                    }
                }
            }
            __syncthreads();
        }

        const float wiv = d_winv[0];
        #pragma unroll
        for (int ii = 0; ii < 8; ii++) {
            int m = mBase + ty * 8 + ii;
            float sc = d_as1[m] * wiv;
            float4 o;
            float* op = &o.x;
            #pragma unroll
            for (int j = 0; j < 4; j++) {
                float gv = (float)accg[ii][j] * sc;
                float vv = (float)accv[ii][j] * sc;
                op[j] = silu_mul(gv, vv);
            }
            *(float4*)(&d_h[(long long)m * IDIM + nBase + tx * 4]) = o;
        }
    }
}

// =====================================================================
// GEMM2 heterogeneous: grid 512 blocks x 256 thr. Per m-row 16 tiles of
// 128 cols: 11 HMMA [0,1408) + 5 dp4a [1408,2048).
// HMMA stage (20480B x2): A16 @0 (128x80) | B16 @10240 (128x80)
// dp4a: As @0 (8KB) | Bs @8192 (8KB)
// =====================================================================
#define S2 20480

__global__ void __launch_bounds__(256, 3) k_gemm2_mix(float* __restrict__ out) {
    extern __shared__ char smem[];
    const int tid = threadIdx.x;
    const int bx = blockIdx.x;
    const int i16 = bx & 15;
    const int mBase = (bx >> 4) * 128;

    if (i16 < 11) {
        // ======================= HMMA block (N=128) =======================
        const int nBase = i16 * 128;
        const int wid = tid >> 5, l = tid & 31;
        const int wm = wid >> 2, wn = wid & 3;      // warp tile 64 x 32
        const uint32_t sb = smem_u32(smem);

        const char* Ag16 = (const char*)d_hq  + (long long)mBase * (IDIM * 2);
        const char* Bg16 = (const char*)d_wqd + (long long)nBase * (IDIM * 2);

        float acc[4][4][4] = {};

        const uint32_t aoff = (uint32_t)(wm * 64 + (l & 15)) * PITCH + (l >> 4) * 16;
        const uint32_t boff = (uint32_t)(wn * 32 + ((l >> 4) << 3) + (l & 7)) * PITCH
                            + ((l >> 3) & 1) * 16;

        #define G2H_LOAD(buf, kt)                                                    \
        {                                                                            \
            const uint32_t st = sb + (buf) * S2;                                     \
            const int row = tid >> 2, seg = tid & 3;                                 \
            const long long go = (long long)row * (IDIM*2) + (kt) * 64 + seg * 16;   \
            const uint32_t so = (uint32_t)row * PITCH + seg * 16;                    \
            cpa16(st + so, Ag16 + go);                                               \
            cpa16(st + (uint32_t)(row + 64) * PITCH + seg * 16,                      \
                  Ag16 + (long long)(row + 64) * (IDIM*2) + (kt) * 64 + seg * 16);   \
            cpa16(st + 10240 + so, Bg16 + go);                                       \
            cpa16(st + 10240 + (uint32_t)(row + 64) * PITCH + seg * 16,              \
                  Bg16 + (long long)(row + 64) * (IDIM*2) + (kt) * 64 + seg * 16);   \
            cp_commit();                                                             \
        }

        const int NK = IDIM / 32;   // 256 chunks
        G2H_LOAD(0, 0);
        for (int kt = 0; kt < NK; kt++) {
            const int buf = kt & 1;
            if (kt + 1 < NK) {
                G2H_LOAD(buf ^ 1, kt + 1);
                asm volatile("cp.async.wait_group 1;");
            } else {
                asm volatile("cp.async.wait_group 0;");
            }
            __syncthreads();
            const uint32_t As = sb + buf * S2;
            const uint32_t Bs = As + 10240;
            #pragma unroll
            for (int ks = 0; ks < 2; ks++) {
                uint32_t b[2][4];
                ldsm4(b[0], Bs + boff + ks * 32);
                ldsm4(b[1], Bs + boff + 16 * PITCH + ks * 32);
                #pragma unroll
                for (int mf = 0; mf < 4; mf++) {
                    uint32_t a[4];
                    ldsm4(a, As + aoff + mf * (16 * PITCH) + ks * 32);
                    #pragma unroll
                    for (int nf = 0; nf < 4; nf++)
                        mma_bf16(acc[mf][nf], a, &b[nf >> 1][(nf & 1) * 2]);
                }
            }
            __syncthreads();
        }
        #undef G2H_LOAD

        const float wiv = d_winv[1];
        #pragma unroll
        for (int mf = 0; mf < 4; mf++) {
            const int r0 = mBase + wm * 64 + mf * 16 + (l >> 2);
            const float s0 = d_as2[r0] * wiv;
            const float s1 = d_as2[r0 + 8] * wiv;
            float* o0p = out + (long long)r0 * HDIM;
            float* o1p = out + (long long)(r0 + 8) * HDIM;
            #pragma unroll
            for (int nf = 0; nf < 4; nf++) {
                const int c0 = nBase + wn * 32 + nf * 8 + (l & 3) * 2;
                float2 o0, o1;
                o0.x = acc[mf][nf][0] * s0;
                o0.y = acc[mf][nf][1] * s0;
                o1.x = acc[mf][nf][2] * s1;
                o1.y = acc[mf][nf][3] * s1;
                *(float2*)(o0p + c0) = o0;
                *(float2*)(o1p + c0) = o1;
            }
        }
    } else {
        // ======================= dp4a block (N=128) =======================
        const int nBase = 1408 + (i16 - 11) * 128;
        const int KI = IDIM / 4;   // 2048 ints per row
        const int* Ab = (const int*)d_hq8 + (long long)mBase * KI;
        const int* Bb = (const int*)d_wqd8 + (long long)nBase * KI;

        int (*As)[128] = (int(*)[128])(smem);           // 8KB
        int (*Bs)[128] = (int(*)[128])(smem + 8192);    // 8KB

        const int tx = tid & 15, ty = tid >> 4;   // 8 cols x 8 rows per thread
        int acc[8][8] = {};

        for (int kt = 0; kt < IDIM / 64; kt++) {
            const int k0 = kt * 16;
            #pragma unroll
            for (int rr = 0; rr < 2; rr++) {
                int u = tid + rr * 256;
                int m = u >> 2, c = u & 3;
                int4 va = *(const int4*)(Ab + (long long)m * KI + k0 + c * 4);
                As[c * 4 + 0][m] = va.x; As[c * 4 + 1][m] = va.y;
                As[c * 4 + 2][m] = va.z; As[c * 4 + 3][m] = va.w;
                int4 vb = *(const int4*)(Bb + (long long)m * KI + k0 + c * 4);
                Bs[c * 4 + 0][m] = vb.x; Bs[c * 4 + 1][m] = vb.y;
                Bs[c * 4 + 2][m] = vb.z; Bs[c * 4 + 3][m] = vb.w;
            }
            __syncthreads();
            #pragma unroll
            for (int kk = 0; kk < 16; kk++) {
                const int4 a0 = *(const int4*)(&As[kk][ty * 8]);
                const int4 a1 = *(const int4*)(&As[kk][ty * 8 + 4]);
                const int4 b0 = *(const int4*)(&Bs[kk][tx * 8]);
                const int4 b1 = *(const int4*)(&Bs[kk][tx * 8 + 4]);
                int a[8] = {a0.x, a0.y, a0.z, a0.w, a1.x, a1.y, a1.z, a1.w};
                int b[8] = {b0.x, b0.y, b0.z, b0.w, b1.x, b1.y, b1.z, b1.w};
                #pragma unroll
                for (int ii = 0; ii < 8; ii++) {
                    #pragma unroll
                    for (int j = 0; j < 8; j++)
                        acc[ii][j] = __dp4a(a[ii], b[j], acc[ii][j]);
                }
            }
            __syncthreads();
        }

        const float wiv = d_winv[1];
        #pragma unroll
        for (int ii = 0; ii < 8; ii++) {
            int m = mBase + ty * 8 + ii;
            float sc = d_as2[m] * wiv;
            float4 o0, o1;
            o0.x = (float)acc[ii][0] * sc; o0.y = (float)acc[ii][1] * sc;
            o0.z = (float)acc[ii][2] * sc; o0.w = (float)acc[ii][3] * sc;
            o1.x = (float)acc[ii][4] * sc; o1.y = (float)acc[ii][5] * sc;
            o1.z = (float)acc[ii][6] * sc; o1.w = (float)acc[ii][7] * sc;
            *(float4*)(&out[(long long)m * HDIM + nBase + tx * 8])     = o0;
            *(float4*)(&out[(long long)m * HDIM + nBase + tx * 8 + 4]) = o1;
        }
    }
}

// ---------------- host ----------------
extern "C" void kernel_launch(void* const* d_in, const int* in_sizes, int n_in,
                              void* d_out, int out_size) {
    const float* x      = (const float*)d_in[0];
    const float* w_gate = (const float*)d_in[1];
    const float* g_gate = (const float*)d_in[2];
    const float* w_down = (const float*)d_in[3];
    const float* g_down = (const float*)d_in[4];
    float* out = (float*)d_out;

    __nv_bfloat16* p_xq = nullptr; signed char* p_xq8 = nullptr; float* p_as1 = nullptr;
    float* p_h = nullptr; __nv_bfloat16* p_hq = nullptr; signed char* p_hq8 = nullptr;
    float* p_as2 = nullptr;
    cudaGetSymbolAddress((void**)&p_xq,  d_xq);
    cudaGetSymbolAddress((void**)&p_xq8, d_xq8);
    cudaGetSymbolAddress((void**)&p_as1, d_as1);
    cudaGetSymbolAddress((void**)&p_h,   d_h);
    cudaGetSymbolAddress((void**)&p_hq,  d_hq);
    cudaGetSymbolAddress((void**)&p_hq8, d_hq8);
    cudaGetSymbolAddress((void**)&p_as2, d_as2);

    const int SM1 = 2 * S1;   // 40960
    const int SM2 = 2 * S2;   // 40960
    cudaFuncSetAttribute(k_gemm1_mix, cudaFuncAttributeMaxDynamicSharedMemorySize, SM1);
    cudaFuncSetAttribute(k_gemm2_mix, cudaFuncAttributeMaxDynamicSharedMemorySize, SM2);

    // 1) weight scales + ternarize (dual format)
    k_abssum2<<<3072, 256>>>(w_gate, w_down);
    k_wscale<<<1, 256>>>();
    k_wquant2<<<6144, 256>>>((const float4*)w_gate, (const float4*)w_down);

    // 2) RMSNorm + quantize x (dual format)
    k_actquant<HDIM, HDIM / 256><<<T_TOK, 256>>>(x, g_gate, p_xq, p_xq8, p_as1);

    // 3) GEMM1 + SwiGLU -> h  (heterogeneous HMMA + dp4a blocks)
    k_gemm1_mix<<<4096, 256, SM1>>>();

    // 4) RMSNorm + quantize h (dual format)
    k_actquant<IDIM, IDIM / 256><<<T_TOK, 256>>>(p_h, g_down, p_hq, p_hq8, p_as2);

    // 5) GEMM2 -> out (heterogeneous)
    k_gemm2_mix<<<512, 256, SM2>>>(out);
}

// round 13
// speedup vs baseline: 1.3354x; 1.3354x over previous
#include <cuda_runtime.h>
#include <cuda_bf16.h>
#include <math.h>
#include <stdint.h>

// Problem dims (fixed): x [2,2048,2048] -> T=4096 tokens, H=2048, I=8192
#define T_TOK 4096
#define HDIM  2048
#define IDIM  8192
#define NGATE 16384   // 2*I rows in w_gate
#define PITCH 80      // padded smem row pitch (bytes) for 64B bf16 k-chunks

// ---------------- device scratch (static, allocation-free) ----------------
__device__ double        d_part[3072];
__device__ float         d_wscale[2];
__device__ float         d_winv[2];
__device__ __nv_bfloat16 d_wqg[(long long)NGATE * HDIM];   // ternary gate/up (bf16 ints)
__device__ __nv_bfloat16 d_wqd[(long long)HDIM * IDIM];
__device__ signed char   d_wqg8[(long long)NGATE * HDIM];  // same values, int8
__device__ signed char   d_wqd8[(long long)HDIM * IDIM];
__device__ __nv_bfloat16 d_xq[(long long)T_TOK * HDIM];    // quant acts L1
__device__ signed char   d_xq8[(long long)T_TOK * HDIM];
__device__ float         d_as1[T_TOK];
__device__ float         d_h[(long long)T_TOK * IDIM];     // SwiGLU output (fp32)
__device__ __nv_bfloat16 d_hq[(long long)T_TOK * IDIM];    // quant acts L2
__device__ signed char   d_hq8[(long long)T_TOK * IDIM];
__device__ float         d_as2[T_TOK];

// ---------------- PTX helpers (base PTX only) ----------------
__device__ __forceinline__ uint32_t smem_u32(const void* p) {
    return (uint32_t)__cvta_generic_to_shared(p);
}
__device__ __forceinline__ void cpa16(uint32_t s, const void* g) {
    asm volatile("cp.async.cg.shared.global [%0], [%1], 16;" :: "r"(s), "l"(g));
}
__device__ __forceinline__ void cp_commit() {
    asm volatile("cp.async.commit_group;");
}
__device__ __forceinline__ void ldsm4(uint32_t* r, uint32_t a) {
    asm volatile("ldmatrix.sync.aligned.m8n8.x4.shared.b16 {%0,%1,%2,%3}, [%4];"
        : "=r"(r[0]), "=r"(r[1]), "=r"(r[2]), "=r"(r[3]) : "r"(a));
}
__device__ __forceinline__ void ldsm2(uint32_t* r, uint32_t a) {
    asm volatile("ldmatrix.sync.aligned.m8n8.x2.shared.b16 {%0,%1}, [%2];"
        : "=r"(r[0]), "=r"(r[1]) : "r"(a));
}
__device__ __forceinline__ void mma_bf16(float* c, const uint32_t* a, const uint32_t* b) {
    asm volatile(
        "mma.sync.aligned.m16n8k16.row.col.f32.bf16.bf16.f32 "
        "{%0,%1,%2,%3}, {%4,%5,%6,%7}, {%8,%9}, {%0,%1,%2,%3};"
        : "+f"(c[0]), "+f"(c[1]), "+f"(c[2]), "+f"(c[3])
        : "r"(a[0]), "r"(a[1]), "r"(a[2]), "r"(a[3]), "r"(b[0]), "r"(b[1]));
}
__device__ __forceinline__ float silu_mul(float g, float v) {
    return g / (1.f + expf(-g)) * v;
}

// ---------------- scalar pre-passes ----------------
__global__ void k_abssum2(const float* __restrict__ wg, const float* __restrict__ wd) {
    const float* w; long long n; int bid, nb;
    if (blockIdx.x < 2048) { w = wg; n = (long long)NGATE * HDIM; bid = blockIdx.x; nb = 2048; }
    else                   { w = wd; n = (long long)HDIM * IDIM;  bid = blockIdx.x - 2048; nb = 1024; }
    float s = 0.f;
    long long stride = (long long)nb * 256;
    for (long long i = (long long)bid * 256 + threadIdx.x; i < n; i += stride)
        s += fabsf(w[i]);
    #pragma unroll
    for (int o = 16; o > 0; o >>= 1) s += __shfl_xor_sync(0xffffffffu, s, o);
    __shared__ double sb[8];
    int wid = threadIdx.x >> 5, lane = threadIdx.x & 31;
    if (lane == 0) sb[wid] = (double)s;
    __syncthreads();
    if (threadIdx.x == 0) {
        double t = 0.0;
        #pragma unroll
        for (int i = 0; i < 8; i++) t += sb[i];
        d_part[blockIdx.x] = t;
    }
}

__global__ void k_wscale() {
    double s0 = 0.0, s1 = 0.0;
    for (int i = threadIdx.x; i < 2048; i += 256) s0 += d_part[i];
    for (int i = 2048 + threadIdx.x; i < 3072; i += 256) s1 += d_part[i];
    #pragma unroll
    for (int o = 16; o > 0; o >>= 1) {
        s0 += __shfl_xor_sync(0xffffffffu, s0, o);
        s1 += __shfl_xor_sync(0xffffffffu, s1, o);
    }
    __shared__ double sb0[8], sb1[8];
    int wid = threadIdx.x >> 5, lane = threadIdx.x & 31;
    if (lane == 0) { sb0[wid] = s0; sb1[wid] = s1; }
    __syncthreads();
    if (threadIdx.x == 0) {
        double t0 = 0.0, t1 = 0.0;
        #pragma unroll
        for (int i = 0; i < 8; i++) { t0 += sb0[i]; t1 += sb1[i]; }
        float m0 = (float)(t0 / (double)((long long)NGATE * HDIM));
        float m1 = (float)(t1 / (double)((long long)HDIM * IDIM));
        float sc0 = 1.f / fmaxf(m0, 1e-5f);
        float sc1 = 1.f / fmaxf(m1, 1e-5f);
        d_wscale[0] = sc0; d_wscale[1] = sc1;
        d_winv[0] = 1.f / sc0; d_winv[1] = 1.f / sc1;
    }
}

// ternarize -> bf16 AND int8
__global__ void k_wquant2(const float4* __restrict__ wg, const float4* __restrict__ wd) {
    const float4* w; long long n4; int which, bid, nb;
    if (blockIdx.x < 4096) { w = wg; n4 = (long long)NGATE * HDIM / 4; which = 0; bid = blockIdx.x; nb = 4096; }
    else                   { w = wd; n4 = (long long)HDIM * IDIM / 4;  which = 1; bid = blockIdx.x - 4096; nb = 2048; }
    float s = d_wscale[which];
    __nv_bfloat162* q2 = reinterpret_cast<__nv_bfloat162*>(which ? d_wqd : d_wqg);
    char4* q8 = reinterpret_cast<char4*>(which ? d_wqd8 : d_wqg8);
    long long stride = (long long)nb * 256;
    for (long long i = (long long)bid * 256 + threadIdx.x; i < n4; i += stride) {
        float4 v = w[i];
        float a = fminf(fmaxf(rintf(v.x * s), -1.f), 1.f);
        float b = fminf(fmaxf(rintf(v.y * s), -1.f), 1.f);
        float c = fminf(fmaxf(rintf(v.z * s), -1.f), 1.f);
        float d = fminf(fmaxf(rintf(v.w * s), -1.f), 1.f);
        q2[i * 2 + 0] = __floats2bfloat162_rn(a, b);
        q2[i * 2 + 1] = __floats2bfloat162_rn(c, d);
        q8[i] = make_char4((signed char)a, (signed char)b, (signed char)c, (signed char)d);
    }
}

// ---------------- block reduction helper ----------------
__device__ __forceinline__ float block_reduce(float v, bool isMax) {
    __shared__ float sb[8];
    __syncthreads();
    #pragma unroll
    for (int o = 16; o > 0; o >>= 1) {
        float t = __shfl_xor_sync(0xffffffffu, v, o);
        v = isMax ? fmaxf(v, t) : (v + t);
    }
    int wid = threadIdx.x >> 5, lane = threadIdx.x & 31;
    if (lane == 0) sb[wid] = v;
    __syncthreads();
    float r;
    if (isMax) {
        r = fmaxf(fmaxf(fmaxf(sb[0], sb[1]), fmaxf(sb[2], sb[3])),
                  fmaxf(fmaxf(sb[4], sb[5]), fmaxf(sb[6], sb[7])));
    } else {
        r = sb[0] + sb[1] + sb[2] + sb[3] + sb[4] + sb[5] + sb[6] + sb[7];
    }
    return r;
}

// ---------------- RMSNorm + per-token int8 quant (bf16 + s8 out) -----------
template <int HID, int VPT>
__global__ void __launch_bounds__(256) k_actquant(
    const float* __restrict__ x, const float* __restrict__ g,
    __nv_bfloat16* __restrict__ q16, signed char* __restrict__ q8,
    float* __restrict__ ascale)
{
    long long t = blockIdx.x;
    const float* xr = x + t * HID;
    float v[VPT];
    float ss = 0.f;
    #pragma unroll
    for (int j = 0; j < VPT; j++) {
        float f = xr[threadIdx.x + j * 256];
        v[j] = f;
        ss += f * f;
    }
    float var = block_reduce(ss, false) * (1.f / (float)HID);
    float r = rsqrtf(var + 1e-5f);
    float amax = 0.f;
    #pragma unroll
    for (int j = 0; j < VPT; j++) {
        float xn = v[j] * r * g[threadIdx.x + j * 256];
        v[j] = xn;
        amax = fmaxf(amax, fabsf(xn));
    }
    amax = block_reduce(amax, true);
    float s = 127.f / fmaxf(amax, 1e-5f);
    __nv_bfloat16* qr = q16 + t * HID;
    signed char* qr8 = q8 + t * HID;
    #pragma unroll
    for (int j = 0; j < VPT; j++) {
        float qf = fminf(fmaxf(rintf(v[j] * s), -128.f), 127.f);
        qr[threadIdx.x + j * 256] = __float2bfloat16(qf);
        qr8[threadIdx.x + j * 256] = (signed char)qf;
    }
    if (threadIdx.x == 0) ascale[t] = 1.f / s;
}

// =====================================================================
// GEMM1 heterogeneous, reg-budgeted. Grid 8192 blocks x 256 thr.
// Per 32 consecutive blocks: 23 HMMA + 9 dp4a. All tiles M=128 x N=32
// h-cols (gate AND v). HMMA covers col-tiles [0,184), dp4a [184,256).
// HMMA stage (15360B x2): A16 @0 (128x80) | G16 @10240 (32x80) | V16 @12800
// dp4a (12288B static view of same smem): As 16x128 | Bg 16x32 | Bv 16x32
// =====================================================================
#define S1H 15360

__global__ void __launch_bounds__(256, 3) k_gemm1_mix() {
    extern __shared__ char smem[];
    const int tid = threadIdx.x;
    const int bx = blockIdx.x;
    const int slot = bx & 31;
    const int grp = bx >> 5;           // 0..255
    const int mrow = grp & 31, seg = grp >> 5;   // seg 0..7
    const int mBase = mrow * 128;

    if (slot < 23) {
        // ===================== HMMA role =====================
        const int ct = seg * 23 + slot;          // 0..183
        const int nBase = ct * 32;
        const int wid = tid >> 5, l = tid & 31;
        const int wm = wid >> 2, wn = wid & 3;   // warp tile M64 x N8
        const uint32_t sb = smem_u32(smem);

        const char* Ag16 = (const char*)d_xq  + (long long)mBase * (HDIM * 2);
        const char* Gg16 = (const char*)d_wqg + (long long)nBase * (HDIM * 2);
        const char* Vg16 = (const char*)d_wqg + (long long)(nBase + IDIM) * (HDIM * 2);

        float accg[16] = {};   // [mf*4 + r]
        float accv[16] = {};

        const uint32_t aoff = (uint32_t)(wm * 64 + (l & 15)) * PITCH + (l >> 4) * 16;
        const uint32_t boff = (uint32_t)(wn * 8 + (l & 7)) * PITCH + ((l >> 3) & 1) * 16;

        #define G1H_LOAD(buf, kt)                                                    \
        {                                                                            \
            const uint32_t st = sb + (buf) * S1H;                                    \
            const int r = tid >> 1, sp = (tid & 1) * 2;                              \
            const char* ga = Ag16 + (long long)r * (HDIM * 2) + (kt) * 64 + sp * 16; \
            cpa16(st + (uint32_t)r * PITCH + sp * 16, ga);                           \
            cpa16(st + (uint32_t)r * PITCH + sp * 16 + 16, ga + 16);                 \
            if (tid < 128) {                                                         \
                int rw = tid >> 2, sg2 = tid & 3;                                    \
                cpa16(st + 10240 + (uint32_t)rw * PITCH + sg2 * 16,                  \
                      Gg16 + (long long)rw * (HDIM * 2) + (kt) * 64 + sg2 * 16);     \
            } else {                                                                 \
                int u = tid - 128, rw = u >> 2, sg2 = u & 3;                         \
                cpa16(st + 12800 + (uint32_t)rw * PITCH + sg2 * 16,                  \
                      Vg16 + (long long)rw * (HDIM * 2) + (kt) * 64 + sg2 * 16);     \
            }                                                                        \
            cp_commit();                                                             \
        }

        const int NK = HDIM / 32;   // 64 chunks
        G1H_LOAD(0, 0);
        for (int kt = 0; kt < NK; kt++) {
            const int buf = kt & 1;
            if (kt + 1 < NK) {
                G1H_LOAD(buf ^ 1, kt + 1);
                asm volatile("cp.async.wait_group 1;");
            } else {
                asm volatile("cp.async.wait_group 0;");
            }
            __syncthreads();
            const uint32_t As = sb + buf * S1H;
            const uint32_t Gs = As + 10240, Vs = As + 12800;
            #pragma unroll
            for (int ks = 0; ks < 2; ks++) {
                uint32_t bg[2], bv[2];
                ldsm2(bg, Gs + boff + ks * 32);
                ldsm2(bv, Vs + boff + ks * 32);
                #pragma unroll
                for (int mf = 0; mf < 4; mf++) {
                    uint32_t a[4];
                    ldsm4(a, As + aoff + mf * (16 * PITCH) + ks * 32);
                    mma_bf16(accg + mf * 4, a, bg);
                    mma_bf16(accv + mf * 4, a, bv);
                }
            }
            __syncthreads();
        }
        #undef G1H_LOAD

        const float wiv = d_winv[0];
        #pragma unroll
        for (int mf = 0; mf < 4; mf++) {
            const int r0 = mBase + wm * 64 + mf * 16 + (l >> 2);
            const float s0 = d_as1[r0] * wiv;
            const float s1 = d_as1[r0 + 8] * wiv;
            const int c0 = nBase + wn * 8 + (l & 3) * 2;
            float2 o0, o1;
            o0.x = silu_mul(accg[mf * 4 + 0] * s0, accv[mf * 4 + 0] * s0);
            o0.y = silu_mul(accg[mf * 4 + 1] * s0, accv[mf * 4 + 1] * s0);
            o1.x = silu_mul(accg[mf * 4 + 2] * s1, accv[mf * 4 + 2] * s1);
            o1.y = silu_mul(accg[mf * 4 + 3] * s1, accv[mf * 4 + 3] * s1);
            *(float2*)(d_h + (long long)r0 * IDIM + c0) = o0;
            *(float2*)(d_h + (long long)(r0 + 8) * IDIM + c0) = o1;
        }
    } else {
        // ===================== dp4a role =====================
        const int ct = 184 + seg * 9 + (slot - 23);   // 184..255
        const int nBase = ct * 32;
        const int KI = HDIM / 4;    // 512 ints per row
        const int* Ab = (const int*)d_xq8  + (long long)mBase * KI;
        const int* Gb = (const int*)d_wqg8 + (long long)nBase * KI;
        const int* Vb = (const int*)d_wqg8 + (long long)(nBase + IDIM) * KI;

        int (*As)[128] = (int(*)[128])(smem);          // 8KB
        int (*Bg)[32]  = (int(*)[32])(smem + 8192);    // 2KB
        int (*Bv)[32]  = (int(*)[32])(smem + 10240);   // 2KB

        const int tx = tid & 15, ty = tid >> 4;   // 16x16 thread grid
        int accg[8][2] = {};
        int accv[8][2] = {};

        for (int kt = 0; kt < HDIM / 64; kt++) {   // 32 chunks of k=64
            const int k0 = kt * 16;
            #pragma unroll
            for (int rr = 0; rr < 2; rr++) {
                int u = tid + rr * 256;
                int m = u >> 2, c = u & 3;
                int4 va = *(const int4*)(Ab + (long long)m * KI + k0 + c * 4);
                As[c * 4 + 0][m] = va.x; As[c * 4 + 1][m] = va.y;
                As[c * 4 + 2][m] = va.z; As[c * 4 + 3][m] = va.w;
            }
            if (tid < 128) {
                int n = tid >> 2, c = tid & 3;
                int4 vg = *(const int4*)(Gb + (long long)n * KI + k0 + c * 4);
                Bg[c * 4 + 0][n] = vg.x; Bg[c * 4 + 1][n] = vg.y;
                Bg[c * 4 + 2][n] = vg.z; Bg[c * 4 + 3][n] = vg.w;
            } else {
                int u = tid - 128, n = u >> 2, c = u & 3;
                int4 vv = *(const int4*)(Vb + (long long)n * KI + k0 + c * 4);
                Bv[c * 4 + 0][n] = vv.x; Bv[c * 4 + 1][n] = vv.y;
                Bv[c * 4 + 2][n] = vv.z; Bv[c * 4 + 3][n] = vv.w;
            }
            __syncthreads();
            #pragma unroll
            for (int kk = 0; kk < 16; kk++) {
                const int4 a0 = *(const int4*)(&As[kk][ty * 8]);
                const int4 a1 = *(const int4*)(&As[kk][ty * 8 + 4]);
                const int2 g2 = *(const int2*)(&Bg[kk][tx * 2]);
                const int2 v2 = *(const int2*)(&Bv[kk][tx * 2]);
                int a[8] = {a0.x, a0.y, a0.z, a0.w, a1.x, a1.y, a1.z, a1.w};
                #pragma unroll
                for (int i = 0; i < 8; i++) {
                    accg[i][0] = __dp4a(a[i], g2.x, accg[i][0]);
                    accg[i][1] = __dp4a(a[i], g2.y, accg[i][1]);
                    accv[i][0] = __dp4a(a[i], v2.x, accv[i][0]);
                    accv[i][1] = __dp4a(a[i], v2.y, accv[i][1]);
                }
            }
            __syncthreads();
        }

        const float wiv = d_winv[0];
        #pragma unroll
        for (int i = 0; i < 8; i++) {
            const int m = mBase + ty * 8 + i;
            const float sc = d_as1[m] * wiv;
            float2 o;
            o.x = silu_mul((float)accg[i][0] * sc, (float)accv[i][0] * sc);
            o.y = silu_mul((float)accg[i][1] * sc, (float)accv[i][1] * sc);
            *(float2*)(d_h + (long long)m * IDIM + nBase + tx * 2) = o;
        }
    }
}

// =====================================================================
// GEMM2 heterogeneous: grid 2048 blocks x 256 thr. Tiles M128 x N32.
// Per 32 blocks: 23 HMMA + 9 dp4a. HMMA col-tiles [0,46), dp4a [46,64).
// HMMA stage (12800B x2): A16 @0 (128x80) | B16 @10240 (32x80)
// dp4a: As 16x128 @0 | Bs 16x32 @8192
// =====================================================================
#define S2H 12800

__global__ void __launch_bounds__(256, 3) k_gemm2_mix(float* __restrict__ out) {
    extern __shared__ char smem[];
    const int tid = threadIdx.x;
    const int bx = blockIdx.x;
    const int slot = bx & 31;
    const int grp = bx >> 5;           // 0..63
    const int mrow = grp & 31, seg = grp >> 5;   // seg 0..1
    const int mBase = mrow * 128;

    if (slot < 23) {
        // ===================== HMMA role =====================
        const int ct = seg * 23 + slot;      // 0..45
        const int nBase = ct * 32;
        const int wid = tid >> 5, l = tid & 31;
        const int wm = wid >> 2, wn = wid & 3;
        const uint32_t sb = smem_u32(smem);

        const char* Ag16 = (const char*)d_hq  + (long long)mBase * (IDIM * 2);
        const char* Bg16 = (const char*)d_wqd + (long long)nBase * (IDIM * 2);

        float acc[16] = {};

        const uint32_t aoff = (uint32_t)(wm * 64 + (l & 15)) * PITCH + (l >> 4) * 16;
        const uint32_t boff = (uint32_t)(wn * 8 + (l & 7)) * PITCH + ((l >> 3) & 1) * 16;

        #define G2H_LOAD(buf, kt)                                                    \
        {                                                                            \
            const uint32_t st = sb + (buf) * S2H;                                    \
            const int r = tid >> 1, sp = (tid & 1) * 2;                              \
            const char* ga = Ag16 + (long long)r * (IDIM * 2) + (kt) * 64 + sp * 16; \
            cpa16(st + (uint32_t)r * PITCH + sp * 16, ga);                           \
            cpa16(st + (uint32_t)r * PITCH + sp * 16 + 16, ga + 16);                 \
            if (tid < 128) {                                                         \
                int rw = tid >> 2, sg2 = tid & 3;                                    \
                cpa16(st + 10240 + (uint32_t)rw * PITCH + sg2 * 16,                  \
                      Bg16 + (long long)rw * (IDIM * 2) + (kt) * 64 + sg2 * 16);     \
            }                                                                        \
            cp_commit();                                                             \
        }

        const int NK = IDIM / 32;   // 256 chunks
        G2H_LOAD(0, 0);
        for (int kt = 0; kt < NK; kt++) {
            const int buf = kt & 1;
            if (kt + 1 < NK) {
                G2H_LOAD(buf ^ 1, kt + 1);
                asm volatile("cp.async.wait_group 1;");
            } else {
                asm volatile("cp.async.wait_group 0;");
            }
            __syncthreads();
            const uint32_t As = sb + buf * S2H;
            const uint32_t Bs = As + 10240;
            #pragma unroll
            for (int ks = 0; ks < 2; ks++) {
                uint32_t b[2];
                ldsm2(b, Bs + boff + ks * 32);
                #pragma unroll
                for (int mf = 0; mf < 4; mf++) {
                    uint32_t a[4];
                    ldsm4(a, As + aoff + mf * (16 * PITCH) + ks * 32);
                    mma_bf16(acc + mf * 4, a, b);
                }
            }
            __syncthreads();
        }
        #undef G2H_LOAD

        const float wiv = d_winv[1];
        #pragma unroll
        for (int mf = 0; mf < 4; mf++) {
            const int r0 = mBase + wm * 64 + mf * 16 + (l >> 2);
            const float s0 = d_as2[r0] * wiv;
            const float s1 = d_as2[r0 + 8] * wiv;
            const int c0 = nBase + wn * 8 + (l & 3) * 2;
            float2 o0, o1;
            o0.x = acc[mf * 4 + 0] * s0;
            o0.y = acc[mf * 4 + 1] * s0;
            o1.x = acc[mf * 4 + 2] * s1;
            o1.y = acc[mf * 4 + 3] * s1;
            *(float2*)(out + (long long)r0 * HDIM + c0) = o0;
            *(float2*)(out + (long long)(r0 + 8) * HDIM + c0) = o1;
        }
    } else {
        // ===================== dp4a role =====================
        const int ct = 46 + seg * 9 + (slot - 23);   // 46..63
        const int nBase = ct * 32;
        const int KI = IDIM / 4;    // 2048 ints per row
        const int* Ab = (const int*)d_hq8  + (long long)mBase * KI;
        const int* Bb = (const int*)d_wqd8 + (long long)nBase * KI;

        int (*As)[128] = (int(*)[128])(smem);          // 8KB
        int (*Bs)[32]  = (int(*)[32])(smem + 8192);    // 2KB

        const int tx = tid & 15, ty = tid >> 4;
        int acc[8][2] = {};

        for (int kt = 0; kt < IDIM / 64; kt++) {   // 128 chunks
            const int k0 = kt * 16;
            #pragma unroll
            for (int rr = 0; rr < 2; rr++) {
                int u = tid + rr * 256;
                int m = u >> 2, c = u & 3;
                int4 va = *(const int4*)(Ab + (long long)m * KI + k0 + c * 4);
                As[c * 4 + 0][m] = va.x; As[c * 4 + 1][m] = va.y;
                As[c * 4 + 2][m] = va.z; As[c * 4 + 3][m] = va.w;
            }
            if (tid < 128) {
                int n = tid >> 2, c = tid & 3;
                int4 vb = *(const int4*)(Bb + (long long)n * KI + k0 + c * 4);
                Bs[c * 4 + 0][n] = vb.x; Bs[c * 4 + 1][n] = vb.y;
                Bs[c * 4 + 2][n] = vb.z; Bs[c * 4 + 3][n] = vb.w;
            }
            __syncthreads();
            #pragma unroll
            for (int kk = 0; kk < 16; kk++) {
                const int4 a0 = *(const int4*)(&As[kk][ty * 8]);
                const int4 a1 = *(const int4*)(&As[kk][ty * 8 + 4]);
                const int2 b2 = *(const int2*)(&Bs[kk][tx * 2]);
                int a[8] = {a0.x, a0.y, a0.z, a0.w, a1.x, a1.y, a1.z, a1.w};
                #pragma unroll
                for (int i = 0; i < 8; i++) {
                    acc[i][0] = __dp4a(a[i], b2.x, acc[i][0]);
                    acc[i][1] = __dp4a(a[i], b2.y, acc[i][1]);
                }
            }
            __syncthreads();
        }

        const float wiv = d_winv[1];
        #pragma unroll
        for (int i = 0; i < 8; i++) {
            const int m = mBase + ty * 8 + i;
            const float sc = d_as2[m] * wiv;
            float2 o;
            o.x = (float)acc[i][0] * sc;
            o.y = (float)acc[i][1] * sc;
            *(float2*)(out + (long long)m * HDIM + nBase + tx * 2) = o;
        }
    }
}

// ---------------- host ----------------
extern "C" void kernel_launch(void* const* d_in, const int* in_sizes, int n_in,
                              void* d_out, int out_size) {
    const float* x      = (const float*)d_in[0];
    const float* w_gate = (const float*)d_in[1];
    const float* g_gate = (const float*)d_in[2];
    const float* w_down = (const float*)d_in[3];
    const float* g_down = (const float*)d_in[4];
    float* out = (float*)d_out;

    __nv_bfloat16* p_xq = nullptr; signed char* p_xq8 = nullptr; float* p_as1 = nullptr;
    float* p_h = nullptr; __nv_bfloat16* p_hq = nullptr; signed char* p_hq8 = nullptr;
    float* p_as2 = nullptr;
    cudaGetSymbolAddress((void**)&p_xq,  d_xq);
    cudaGetSymbolAddress((void**)&p_xq8, d_xq8);
    cudaGetSymbolAddress((void**)&p_as1, d_as1);
    cudaGetSymbolAddress((void**)&p_h,   d_h);
    cudaGetSymbolAddress((void**)&p_hq,  d_hq);
    cudaGetSymbolAddress((void**)&p_hq8, d_hq8);
    cudaGetSymbolAddress((void**)&p_as2, d_as2);

    const int SM1 = 2 * S1H;   // 30720
    const int SM2 = 2 * S2H;   // 25600
    cudaFuncSetAttribute(k_gemm1_mix, cudaFuncAttributeMaxDynamicSharedMemorySize, SM1);
    cudaFuncSetAttribute(k_gemm2_mix, cudaFuncAttributeMaxDynamicSharedMemorySize, SM2);

    // 1) weight scales + ternarize (dual format)
    k_abssum2<<<3072, 256>>>(w_gate, w_down);
    k_wscale<<<1, 256>>>();
    k_wquant2<<<6144, 256>>>((const float4*)w_gate, (const float4*)w_down);

    // 2) RMSNorm + quantize x (dual format)
    k_actquant<HDIM, HDIM / 256><<<T_TOK, 256>>>(x, g_gate, p_xq, p_xq8, p_as1);

    // 3) GEMM1 + SwiGLU -> h (heterogeneous, reg-budgeted)
    k_gemm1_mix<<<8192, 256, SM1>>>();

    // 4) RMSNorm + quantize h (dual format)
    k_actquant<IDIM, IDIM / 256><<<T_TOK, 256>>>(p_h, g_down, p_hq, p_hq8, p_as2);

    // 5) GEMM2 -> out (heterogeneous)
    k_gemm2_mix<<<2048, 256, SM2>>>(out);
}

// round 16
// speedup vs baseline: 2.2261x; 1.6671x over previous
#include <cuda_runtime.h>
#include <cuda_bf16.h>
#include <math.h>
#include <stdint.h>

// Problem dims (fixed): x [2,2048,2048] -> T=4096 tokens, H=2048, I=8192
#define T_TOK 4096
#define HDIM  2048
#define IDIM  8192
#define NGATE 16384   // 2*I rows in w_gate
#define PITCH 80      // padded smem row pitch (bytes) for 64B k-chunks

// ---------------- device scratch (static, allocation-free) ----------------
__device__ double        d_part[3072];    // per-block |w| partial sums
__device__ float         d_wscale[2];
__device__ float         d_winv[2];
__device__ __nv_bfloat16 d_wqg[(long long)NGATE * HDIM];  // ternary gate/up (bf16 ints)
__device__ __nv_bfloat16 d_wqd[(long long)HDIM * IDIM];   // ternary down
__device__ __nv_bfloat16 d_xq[(long long)T_TOK * HDIM];   // quant acts L1 (bf16 ints)
__device__ float         d_as1[T_TOK];
__device__ float         d_h[(long long)T_TOK * IDIM];    // SwiGLU output (fp32)
__device__ __nv_bfloat16 d_hq[(long long)T_TOK * IDIM];   // quant acts L2
__device__ float         d_as2[T_TOK];

// ---------------- PTX helpers (base PTX only; valid at sm_103 target) ------
__device__ __forceinline__ uint32_t smem_u32(const void* p) {
    return (uint32_t)__cvta_generic_to_shared(p);
}
__device__ __forceinline__ void cpa16(uint32_t s, const void* g) {
    asm volatile("cp.async.cg.shared.global [%0], [%1], 16;" :: "r"(s), "l"(g));
}
__device__ __forceinline__ void cp_commit() {
    asm volatile("cp.async.commit_group;");
}
__device__ __forceinline__ void ldsm4(uint32_t* r, uint32_t a) {
    asm volatile("ldmatrix.sync.aligned.m8n8.x4.shared.b16 {%0,%1,%2,%3}, [%4];"
        : "=r"(r[0]), "=r"(r[1]), "=r"(r[2]), "=r"(r[3]) : "r"(a));
}
__device__ __forceinline__ void mma_bf16(float* c, const uint32_t* a, const uint32_t* b) {
    asm volatile(
        "mma.sync.aligned.m16n8k16.row.col.f32.bf16.bf16.f32 "
        "{%0,%1,%2,%3}, {%4,%5,%6,%7}, {%8,%9}, {%0,%1,%2,%3};"
        : "+f"(c[0]), "+f"(c[1]), "+f"(c[2]), "+f"(c[3])
        : "r"(a[0]), "r"(a[1]), "r"(a[2]), "r"(a[3]), "r"(b[0]), "r"(b[1]));
}
__device__ __forceinline__ float silu_mul(float g, float v) {
    return g / (1.f + expf(-g)) * v;
}

// ---------------- scalar pre-passes ----------------
// partial |w| sums: blocks [0,2048) gate, [2048,3072) down; no atomics
__global__ void k_abssum2(const float* __restrict__ wg, const float* __restrict__ wd) {
    const float* w; long long n; int bid, nb;
    if (blockIdx.x < 2048) { w = wg; n = (long long)NGATE * HDIM; bid = blockIdx.x; nb = 2048; }
    else                   { w = wd; n = (long long)HDIM * IDIM;  bid = blockIdx.x - 2048; nb = 1024; }
    float s = 0.f;
    long long stride = (long long)nb * 256;
    for (long long i = (long long)bid * 256 + threadIdx.x; i < n; i += stride)
        s += fabsf(w[i]);
    #pragma unroll
    for (int o = 16; o > 0; o >>= 1) s += __shfl_xor_sync(0xffffffffu, s, o);
    __shared__ double sb[8];
    int wid = threadIdx.x >> 5, lane = threadIdx.x & 31;
    if (lane == 0) sb[wid] = (double)s;
    __syncthreads();
    if (threadIdx.x == 0) {
        double t = 0.0;
        #pragma unroll
        for (int i = 0; i < 8; i++) t += sb[i];
        d_part[blockIdx.x] = t;
    }
}

__global__ void k_wscale() {
    double s0 = 0.0, s1 = 0.0;
    for (int i = threadIdx.x; i < 2048; i += 256) s0 += d_part[i];
    for (int i = 2048 + threadIdx.x; i < 3072; i += 256) s1 += d_part[i];
    #pragma unroll
    for (int o = 16; o > 0; o >>= 1) {
        s0 += __shfl_xor_sync(0xffffffffu, s0, o);
        s1 += __shfl_xor_sync(0xffffffffu, s1, o);
    }
    __shared__ double sb0[8], sb1[8];
    int wid = threadIdx.x >> 5, lane = threadIdx.x & 31;
    if (lane == 0) { sb0[wid] = s0; sb1[wid] = s1; }
    __syncthreads();
    if (threadIdx.x == 0) {
        double t0 = 0.0, t1 = 0.0;
        #pragma unroll
        for (int i = 0; i < 8; i++) { t0 += sb0[i]; t1 += sb1[i]; }
        float m0 = (float)(t0 / (double)((long long)NGATE * HDIM));
        float m1 = (float)(t1 / (double)((long long)HDIM * IDIM));
        float sc0 = 1.f / fmaxf(m0, 1e-5f);
        float sc1 = 1.f / fmaxf(m1, 1e-5f);
        d_wscale[0] = sc0; d_wscale[1] = sc1;
        d_winv[0] = 1.f / sc0; d_winv[1] = 1.f / sc1;
    }
}

// ternarize both weights -> bf16; blocks [0,4096) gate, [4096,6144) down
__global__ void k_wquant2(const float4* __restrict__ wg, const float4* __restrict__ wd) {
    const float4* w; long long n4; int which, bid, nb;
    if (blockIdx.x < 4096) { w = wg; n4 = (long long)NGATE * HDIM / 4; which = 0; bid = blockIdx.x; nb = 4096; }
    else                   { w = wd; n4 = (long long)HDIM * IDIM / 4;  which = 1; bid = blockIdx.x - 4096; nb = 2048; }
    float s = d_wscale[which];
    __nv_bfloat162* q2 = reinterpret_cast<__nv_bfloat162*>(which ? d_wqd : d_wqg);
    long long stride = (long long)nb * 256;
    for (long long i = (long long)bid * 256 + threadIdx.x; i < n4; i += stride) {
        float4 v = w[i];
        float a = fminf(fmaxf(rintf(v.x * s), -1.f), 1.f);
        float b = fminf(fmaxf(rintf(v.y * s), -1.f), 1.f);
        float c = fminf(fmaxf(rintf(v.z * s), -1.f), 1.f);
        float d = fminf(fmaxf(rintf(v.w * s), -1.f), 1.f);
        q2[i * 2 + 0] = __floats2bfloat162_rn(a, b);
        q2[i * 2 + 1] = __floats2bfloat162_rn(c, d);
    }
}

// ---------------- block reduction helper ----------------
__device__ __forceinline__ float block_reduce(float v, bool isMax) {
    __shared__ float sb[8];
    __syncthreads();
    #pragma unroll
    for (int o = 16; o > 0; o >>= 1) {
        float t = __shfl_xor_sync(0xffffffffu, v, o);
        v = isMax ? fmaxf(v, t) : (v + t);
    }
    int wid = threadIdx.x >> 5, lane = threadIdx.x & 31;
    if (lane == 0) sb[wid] = v;
    __syncthreads();
    float r;
    if (isMax) {
        r = fmaxf(fmaxf(fmaxf(sb[0], sb[1]), fmaxf(sb[2], sb[3])),
                  fmaxf(fmaxf(sb[4], sb[5]), fmaxf(sb[6], sb[7])));
    } else {
        r = sb[0] + sb[1] + sb[2] + sb[3] + sb[4] + sb[5] + sb[6] + sb[7];
    }
    return r;
}

// ---------------- RMSNorm + per-token int8 quant (vectorized) --------------
// VPT4 = HID / (256 threads * 4 elems)
template <int HID, int VPT4>
__global__ void __launch_bounds__(256) k_actquant(
    const float* __restrict__ x, const float* __restrict__ g,
    __nv_bfloat16* __restrict__ q, float* __restrict__ ascale)
{
    long long t = blockIdx.x;
    const float4* xr = reinterpret_cast<const float4*>(x + t * HID);
    const float4* gr = reinterpret_cast<const float4*>(g);
    float4 v[VPT4];
    float ss = 0.f;
    #pragma unroll
    for (int j = 0; j < VPT4; j++) {
        float4 f = xr[threadIdx.x + j * 256];
        v[j] = f;
        ss += f.x * f.x + f.y * f.y + f.z * f.z + f.w * f.w;
    }
    float var = block_reduce(ss, false) * (1.f / (float)HID);
    float r = rsqrtf(var + 1e-5f);
    float amax = 0.f;
    #pragma unroll
    for (int j = 0; j < VPT4; j++) {
        float4 gg = gr[threadIdx.x + j * 256];
        v[j].x *= r * gg.x;  v[j].y *= r * gg.y;
        v[j].z *= r * gg.z;  v[j].w *= r * gg.w;
        amax = fmaxf(amax, fmaxf(fmaxf(fabsf(v[j].x), fabsf(v[j].y)),
                                 fmaxf(fabsf(v[j].z), fabsf(v[j].w))));
    }
    amax = block_reduce(amax, true);
    float s = 127.f / fmaxf(amax, 1e-5f);
    uint2* qr = reinterpret_cast<uint2*>(q + t * HID);
    #pragma unroll
    for (int j = 0; j < VPT4; j++) {
        float a = fminf(fmaxf(rintf(v[j].x * s), -128.f), 127.f);
        float b = fminf(fmaxf(rintf(v[j].y * s), -128.f), 127.f);
        float c = fminf(fmaxf(rintf(v[j].z * s), -128.f), 127.f);
        float d = fminf(fmaxf(rintf(v[j].w * s), -128.f), 127.f);
        __nv_bfloat162 p0 = __floats2bfloat162_rn(a, b);   // exact ints
        __nv_bfloat162 p1 = __floats2bfloat162_rn(c, d);
        uint2 u;
        u.x = *reinterpret_cast<uint32_t*>(&p0);
        u.y = *reinterpret_cast<uint32_t*>(&p1);
        qr[threadIdx.x + j * 256] = u;
    }
    if (threadIdx.x == 0) ascale[t] = 1.f / s;
}

// =====================================================================
// GEMM1 (HMMA, 16 warps): xq @ w_gate^T fused with SwiGLU.  (R10 verbatim)
// CTA tile M=128 x N=128 h-cols (gate AND v). Warp grid 2(m) x 8(n),
// warp tile M=64 x N=16 per operand. k-chunk = 32 bf16 (64B rows).
// Stage (S1=30720): A16 @0 (128x80) | G16 @10240 | V16 @20480. 2 stages.
// =====================================================================
#define S1 30720

#define G1_LOAD(buf, kt)                                                     \
{                                                                            \
    const uint32_t st = sb + (buf) * S1;                                     \
    const int row = tid >> 2, seg = tid & 3;                                 \
    const long long go = (long long)row * (HDIM * 2) + (kt) * 64 + seg * 16; \
    const uint32_t so = (uint32_t)row * PITCH + seg * 16;                    \
    cpa16(st + so,          Ag16 + go);                                      \
    cpa16(st + 10240 + so,  Gg16 + go);                                      \
    cpa16(st + 20480 + so,  Vg16 + go);                                      \
    cp_commit();                                                             \
}

__global__ void __launch_bounds__(512, 1) k_gemm1() {
    extern __shared__ char smem[];
    const int tid = threadIdx.x;
    const int wid = tid >> 5, l = tid & 31;
    const int wm = wid >> 3, wn = wid & 7;     // 2 x 8 warp grid
    const int mBase = blockIdx.y * 128;
    const int nBase = blockIdx.x * 128;
    const uint32_t sb = smem_u32(smem);

    const char* Ag16 = (const char*)d_xq  + (long long)mBase * (HDIM * 2);
    const char* Gg16 = (const char*)d_wqg + (long long)nBase * (HDIM * 2);
    const char* Vg16 = (const char*)d_wqg + (long long)(nBase + IDIM) * (HDIM * 2);

    float accg[4][2][4] = {};
    float accv[4][2][4] = {};

    const uint32_t aoff = (uint32_t)(wm * 64 + (l & 15)) * PITCH + (l >> 4) * 16;
    const uint32_t boff = (uint32_t)(wn * 16 + ((l >> 4) << 3) + (l & 7)) * PITCH
                        + ((l >> 3) & 1) * 16;

    const int NK = HDIM / 32;   // 64 chunks
    G1_LOAD(0, 0);

    for (int kt = 0; kt < NK; kt++) {
        const int buf = kt & 1;
        if (kt + 1 < NK) {
            G1_LOAD(buf ^ 1, kt + 1);
            asm volatile("cp.async.wait_group 1;");
        } else {
            asm volatile("cp.async.wait_group 0;");
        }
        __syncthreads();
        const uint32_t As = sb + buf * S1;
        const uint32_t Gs = As + 10240, Vs = As + 20480;
        #pragma unroll
        for (int ks = 0; ks < 2; ks++) {
            uint32_t a[4][4];
            #pragma unroll
            for (int mf = 0; mf < 4; mf++)
                ldsm4(a[mf], As + aoff + mf * (16 * PITCH) + ks * 32);
            uint32_t bg[4], bv[4];
            ldsm4(bg, Gs + boff + ks * 32);
            ldsm4(bv, Vs + boff + ks * 32);
            #pragma unroll
            for (int mf = 0; mf < 4; mf++) {
                #pragma unroll
                for (int nf = 0; nf < 2; nf++) {
                    mma_bf16(accg[mf][nf], a[mf], &bg[nf * 2]);
                    mma_bf16(accv[mf][nf], a[mf], &bv[nf * 2]);
                }
            }
        }
        __syncthreads();
    }
    #undef G1_LOAD

    // epilogue: dequant + SwiGLU -> d_h (fp32)
    const float wiv = d_winv[0];
    #pragma unroll
    for (int mf = 0; mf < 4; mf++) {
        const int r0 = mBase + wm * 64 + mf * 16 + (l >> 2);
        const float s0 = d_as1[r0] * wiv;
        const float s1 = d_as1[r0 + 8] * wiv;
        float* h0 = d_h + (long long)r0 * IDIM;
        float* h1 = d_h + (long long)(r0 + 8) * IDIM;
        #pragma unroll
        for (int nf = 0; nf < 2; nf++) {
            const int c0 = nBase + wn * 16 + nf * 8 + (l & 3) * 2;
            float2 o0, o1;
            o0.x = silu_mul(accg[mf][nf][0] * s0, accv[mf][nf][0] * s0);
            o0.y = silu_mul(accg[mf][nf][1] * s0, accv[mf][nf][1] * s0);
            o1.x = silu_mul(accg[mf][nf][2] * s1, accv[mf][nf][2] * s1);
            o1.y = silu_mul(accg[mf][nf][3] * s1, accv[mf][nf][3] * s1);
            *(float2*)(h0 + c0) = o0;
            *(float2*)(h1 + c0) = o1;
        }
    }
}

// =====================================================================
// GEMM2 (HMMA, 8 warps, finer tiles): hq @ w_down^T -> fp32 out.
// CTA tile M=128 x N=64; warp grid 2(m) x 4(n); warp tile M64 x N16.
// 1024 blocks at 2 CTAs/SM -> smaller wave-quantization tail.
// Stage (S2=15360): A16 @0 (128x80) | B16 @10240 (64x80). 2 stages.
// =====================================================================
#define S2 15360

#define G2_LOAD(buf, kt)                                                     \
{                                                                            \
    const uint32_t st = sb + (buf) * S2;                                     \
    const int row = tid >> 2, seg = tid & 3;                                 \
    const long long go = (long long)row * (IDIM * 2) + (kt) * 64 + seg * 16; \
    const uint32_t so = (uint32_t)row * PITCH + seg * 16;                    \
    cpa16(st + so, Ag16 + go);                                               \
    cpa16(st + (uint32_t)(row + 64) * PITCH + seg * 16,                      \
          Ag16 + (long long)(row + 64) * (IDIM * 2) + (kt) * 64 + seg * 16); \
    cpa16(st + 10240 + so, Bg16 + go);                                       \
    cp_commit();                                                             \
}

__global__ void __launch_bounds__(256, 2) k_gemm2(float* __restrict__ out) {
    extern __shared__ char smem[];
    const int tid = threadIdx.x;
    const int wid = tid >> 5, l = tid & 31;
    const int wm = wid >> 2, wn = wid & 3;     // 2 x 4 warp grid
    const int mBase = blockIdx.y * 128;
    const int nBase = blockIdx.x * 64;
    const uint32_t sb = smem_u32(smem);

    const char* Ag16 = (const char*)d_hq  + (long long)mBase * (IDIM * 2);
    const char* Bg16 = (const char*)d_wqd + (long long)nBase * (IDIM * 2);

    float acc[4][2][4] = {};

    const uint32_t aoff = (uint32_t)(wm * 64 + (l & 15)) * PITCH + (l >> 4) * 16;
    const uint32_t boff = (uint32_t)(wn * 16 + ((l >> 4) << 3) + (l & 7)) * PITCH
                        + ((l >> 3) & 1) * 16;

    const int NK = IDIM / 32;   // 256 chunks
    G2_LOAD(0, 0);

    for (int kt = 0; kt < NK; kt++) {
        const int buf = kt & 1;
        if (kt + 1 < NK) {
            G2_LOAD(buf ^ 1, kt + 1);
            asm volatile("cp.async.wait_group 1;");
        } else {
            asm volatile("cp.async.wait_group 0;");
        }
        __syncthreads();
        const uint32_t As = sb + buf * S2;
        const uint32_t Bs = As + 10240;
        #pragma unroll
        for (int ks = 0; ks < 2; ks++) {
            uint32_t a[4][4];
            #pragma unroll
            for (int mf = 0; mf < 4; mf++)
                ldsm4(a[mf], As + aoff + mf * (16 * PITCH) + ks * 32);
            uint32_t b[4];
            ldsm4(b, Bs + boff + ks * 32);
            #pragma unroll
            for (int mf = 0; mf < 4; mf++) {
                #pragma unroll
                for (int nf = 0; nf < 2; nf++)
                    mma_bf16(acc[mf][nf], a[mf], &b[nf * 2]);
            }
        }
        __syncthreads();
    }
    #undef G2_LOAD

    const float wiv = d_winv[1];
    #pragma unroll
    for (int mf = 0; mf < 4; mf++) {
        const int r0 = mBase + wm * 64 + mf * 16 + (l >> 2);
        const float s0 = d_as2[r0] * wiv;
        const float s1 = d_as2[r0 + 8] * wiv;
        float* o0p = out + (long long)r0 * HDIM;
        float* o1p = out + (long long)(r0 + 8) * HDIM;
        #pragma unroll
        for (int nf = 0; nf < 2; nf++) {
            const int c0 = nBase + wn * 16 + nf * 8 + (l & 3) * 2;
            float2 o0, o1;
            o0.x = acc[mf][nf][0] * s0;
            o0.y = acc[mf][nf][1] * s0;
            o1.x = acc[mf][nf][2] * s1;
            o1.y = acc[mf][nf][3] * s1;
            *(float2*)(o0p + c0) = o0;
            *(float2*)(o1p + c0) = o1;
        }
    }
}

// ---------------- host ----------------
extern "C" void kernel_launch(void* const* d_in, const int* in_sizes, int n_in,
                              void* d_out, int out_size) {
    const float* x      = (const float*)d_in[0];
    const float* w_gate = (const float*)d_in[1];
    const float* g_gate = (const float*)d_in[2];
    const float* w_down = (const float*)d_in[3];
    const float* g_down = (const float*)d_in[4];
    float* out = (float*)d_out;

    __nv_bfloat16* p_xq = nullptr; float* p_as1 = nullptr;
    float* p_h = nullptr; __nv_bfloat16* p_hq = nullptr; float* p_as2 = nullptr;
    cudaGetSymbolAddress((void**)&p_xq,  d_xq);
    cudaGetSymbolAddress((void**)&p_as1, d_as1);
    cudaGetSymbolAddress((void**)&p_h,   d_h);
    cudaGetSymbolAddress((void**)&p_hq,  d_hq);
    cudaGetSymbolAddress((void**)&p_as2, d_as2);

    const int SM1 = 2 * S1;   // 61440
    const int SM2 = 2 * S2;   // 30720
    cudaFuncSetAttribute(k_gemm1, cudaFuncAttributeMaxDynamicSharedMemorySize, SM1);
    cudaFuncSetAttribute(k_gemm2, cudaFuncAttributeMaxDynamicSharedMemorySize, SM2);

    // 1) weight scales (no atomics) + ternarize
    k_abssum2<<<3072, 256>>>(w_gate, w_down);
    k_wscale<<<1, 256>>>();
    k_wquant2<<<6144, 256>>>((const float4*)w_gate, (const float4*)w_down);

    // 2) RMSNorm + quantize x (vectorized)
    k_actquant<HDIM, HDIM / 1024><<<T_TOK, 256>>>(x, g_gate, p_xq, p_as1);

    // 3) GEMM1 + SwiGLU -> h  (R10-proven 16-warp HMMA)
    k_gemm1<<<dim3(IDIM / 128, T_TOK / 128), 512, SM1>>>();

    // 4) RMSNorm + quantize h (vectorized)
    k_actquant<IDIM, IDIM / 1024><<<T_TOK, 256>>>(p_h, g_down, p_hq, p_as2);

    // 5) GEMM2 -> out (M128 x N64 tiles, 2 CTAs/SM)
    k_gemm2<<<dim3(HDIM / 64, T_TOK / 128), 256, SM2>>>(out);
}